// round 17
// baseline (speedup 1.0000x reference)
#include <cuda_runtime.h>
#include <math_constants.h>

// Shapes fixed by the problem
#define B_  32
#define T_  12
#define N_  512
#define F_  64
#define H_  64

#define BLOCKS 444             // exactly 3 blocks per SM (148 SMs)
#define THREADS 256
#define WARPS   8
#define TOTAL_WARPS (BLOCKS * WARPS)       // 3552
#define TOTAL_SU 8192                      // 16384 pairs / 2 per su
#define N3WARPS (TOTAL_SU - 2 * TOTAL_WARPS)   // 1088 warps do 3 su, rest 2

// Global accumulator for the 12x12 gram (REDG atomic adds from all blocks).
// Zero at module load; last block resets to 0 each launch.
__device__ float g_score[144];
// Ticket: zero at module load; last block resets to 0 each launch.
__device__ unsigned int g_ticket;

__global__ __launch_bounds__(THREADS, 3) void fft_sel_fused(
    const float* __restrict__ x,   // [B,T,N,F]
    const float* __restrict__ Wq,  // [F,H]
    const float* __restrict__ bq,  // [H]
    const float* __restrict__ Wk,  // [F,H]
    const float* __restrict__ bk,  // [H]
    float* __restrict__ out, int out_n)
{
    __shared__ float s_wq[F_], s_wk[F_];
    __shared__ float s_bsum[2];
    __shared__ float s_q[64 * T_];   // 64 staging slots x 12 t
    __shared__ float s_k[64 * T_];
    __shared__ float s_score[144];
    __shared__ bool  s_last;

    const int tid  = threadIdx.x;
    const int wid  = tid >> 5;
    const int lane = tid & 31;

    // ---- Zero staging slots (warps with 2 su leave slots unused) ----
#pragma unroll
    for (int i = tid; i < 64 * T_; i += THREADS) { s_q[i] = 0.f; s_k[i] = 0.f; }

    // ---- Coalesced pre-sum of weights over H (exact FFT/irfft/mean-H collapse) ----
    {
#pragma unroll
        for (int r = 0; r < 8; r++) {
            const int f = wid * 8 + r;
            float aq = Wq[f * H_ + lane] + Wq[f * H_ + 32 + lane];
            float ak = Wk[f * H_ + lane] + Wk[f * H_ + 32 + lane];
#pragma unroll
            for (int s = 16; s >= 1; s >>= 1) {
                aq += __shfl_xor_sync(0xffffffffu, aq, s);
                ak += __shfl_xor_sync(0xffffffffu, ak, s);
            }
            if (lane == 0) { s_wq[f] = aq; s_wk[f] = ak; }
        }
        if (wid == 0) {
            float a = bq[lane] + bq[32 + lane];
#pragma unroll
            for (int s = 16; s >= 1; s >>= 1) a += __shfl_xor_sync(0xffffffffu, a, s);
            if (lane == 0) s_bsum[0] = a;
        } else if (wid == 1) {
            float a = bk[lane] + bk[32 + lane];
#pragma unroll
            for (int s = 16; s >= 1; s >>= 1) a += __shfl_xor_sync(0xffffffffu, a, s);
            if (lane == 0) s_bsum[1] = a;
        }
    }
    __syncthreads();

    // ---- 8-lane-group streaming: fully line-coalesced loads ----
    // Warp = 4 groups of 8 lanes. A group handles one (pair,row) slot per
    // slot-iter; lane q loads float4s q and q+8 of the 64-float row, so each
    // LDG.128 covers 4 FULL 128B lines -> minimum wavefronts.
    const int g8 = lane >> 3;   // group 0..3
    const int q8 = lane & 7;    // lane within group

    const float4 wq0 = ((const float4*)s_wq)[q8];
    const float4 wq1 = ((const float4*)s_wq)[q8 + 8];
    const float4 wk0 = ((const float4*)s_wk)[q8];
    const float4 wk1 = ((const float4*)s_wk)[q8 + 8];
    const float bqs = s_bsum[0];
    const float bks = s_bsum[1];

    // Slot geometry su-invariant: slot = it*4 + g8, 6 slots cover 24 rows (2 pairs)
    int pr_[6], row_[6];
#pragma unroll
    for (int it = 0; it < 6; it++) {
        const int slot = it * 4 + g8;
        pr_[it]  = slot / 12;
        row_[it] = slot - pr_[it] * 12;
    }

    // Balanced work split at su granularity: first N3WARPS warps take 3 su,
    // the rest take 2. Contiguous su chunks.
    const int gw = blockIdx.x * WARPS + wid;
    int suStart, suCnt;
    if (gw < N3WARPS) { suStart = gw * 3;                          suCnt = 3; }
    else              { suStart = N3WARPS * 3 + (gw - N3WARPS) * 2; suCnt = 2; }

    const float4* __restrict__ x4 = (const float4*)x;

#pragma unroll
    for (int lsu = 0; lsu < 3; lsu++) {
        if (lsu < suCnt) {
            const int pbase = 2 * (suStart + lsu);    // global pair base

            float4 v0[6], v1[6];

            // ---- Load phase: 12 independent, fully-coalesced LDG.128 ----
#pragma unroll
            for (int it = 0; it < 6; it++) {
                const int gp = pbase + pr_[it];
                const int b  = gp >> 9;
                const int n  = gp & 511;
                const size_t rowbase = ((size_t)(b * T_ + row_[it]) * N_ + n) * 16;
                v0[it] = x4[rowbase + q8];
                v1[it] = x4[rowbase + 8 + q8];
            }

            // ---- Reduce phase: 6 independent chains ----
#pragma unroll
            for (int it = 0; it < 6; it++) {
                float aq = v0[it].x * wq0.x + v0[it].y * wq0.y + v0[it].z * wq0.z + v0[it].w * wq0.w
                         + v1[it].x * wq1.x + v1[it].y * wq1.y + v1[it].z * wq1.z + v1[it].w * wq1.w;
                float ak = v0[it].x * wk0.x + v0[it].y * wk0.y + v0[it].z * wk0.z + v0[it].w * wk0.w
                         + v1[it].x * wk1.x + v1[it].y * wk1.y + v1[it].z * wk1.z + v1[it].w * wk1.w;

                // 8-lane reduction (within octet): xor4, xor2, then cross-pack xor1
                float t1 = aq + __shfl_xor_sync(0xffffffffu, aq, 4);
                const float aq2 = t1 + __shfl_xor_sync(0xffffffffu, t1, 2);
                float t2 = ak + __shfl_xor_sync(0xffffffffu, ak, 4);
                const float ak2 = t2 + __shfl_xor_sync(0xffffffffu, t2, 2);
                const float vsel = (q8 & 1) ? aq2 : ak2;
                const float toth = __shfl_xor_sync(0xffffffffu, vsel, 1);

                const int e = wid * 8 + 2 * lsu + pr_[it];   // 0..63 staging slot
                if (q8 == 0) s_q[e * T_ + row_[it]] = aq2 + toth + bqs;
                else if (q8 == 1) s_k[e * T_ + row_[it]] = ak2 + toth + bks;
            }
        }
    }
    __syncthreads();

    // ---- Block-local 12x12 gram over the 64 staging slots,
    //      accumulated globally via REDG ----
    if (tid < 144) {
        const int i = tid / 12;
        const int j = tid - i * 12;
        float acc = 0.f;
#pragma unroll 8
        for (int e = 0; e < 64; e++)
            acc += s_q[e * T_ + i] * s_k[e * T_ + j];
        atomicAdd(&g_score[tid], acc);
    }

    // ---- Last-block ticket ----
    __threadfence();          // publish g_score adds
    __syncthreads();
    if (tid == 0) {
        unsigned int old = atomicAdd(&g_ticket, 1u);
        s_last = (old == BLOCKS - 1u);
    }
    __syncthreads();
    if (!s_last) return;

    __threadfence();          // acquire all blocks' adds

    // ---- Finalize: scale, reset accumulator for next graph replay ----
    if (tid < 144) {
        const float a = g_score[tid];
        // mean over (B, N, H) = / (32*512*64)
        s_score[tid] = a * (1.0f / 1048576.0f);
        g_score[tid] = 0.f;
    }
    __syncthreads();

    if (tid == 0) g_ticket = 0u;   // reset for next graph replay

    // ---- Row-wise top-k (tau from out_size), jax tie-break = lowest index ----
    int tau;
    bool write_idx;
    if (out_n >= 2 * T_ && (out_n % (2 * T_)) == 0) {
        tau = out_n / (2 * T_);
        write_idx = true;
    } else {
        tau = out_n / T_;
        write_idx = false;
    }
    if (tau > T_) tau = T_;

    if (tid < T_) {
        const int i = tid;
        float v2[T_];
#pragma unroll
        for (int j = 0; j < T_; j++) v2[j] = s_score[i * 12 + j];
        unsigned usedmask = 0u;
        for (int r = 0; r < tau; r++) {
            float best = -CUDART_INF_F;
            int bj = 0;
#pragma unroll
            for (int j = 0; j < T_; j++) {
                bool ok = ((usedmask >> j) & 1u) == 0u && v2[j] > best;
                if (ok) { best = v2[j]; bj = j; }
            }
            usedmask |= (1u << bj);
            out[i * tau + r] = best;
            if (write_idx) out[T_ * tau + i * tau + r] = (float)bj;
        }
    }
}

extern "C" void kernel_launch(void* const* d_in, const int* in_sizes, int n_in,
                              void* d_out, int out_size)
{
    const float* x  = (const float*)d_in[0];
    const float* Wq = (const float*)d_in[1];
    const float* bq = (const float*)d_in[2];
    const float* Wk = (const float*)d_in[3];
    const float* bk = (const float*)d_in[4];
    (void)in_sizes; (void)n_in;

    fft_sel_fused<<<BLOCKS, THREADS>>>(x, Wq, bq, Wk, bk, (float*)d_out, out_size);
}